// round 6
// baseline (speedup 1.0000x reference)
#include <cuda_runtime.h>
#include <cuda_bf16.h>

// HalfEdgeConv: out[i] = relu(W @ concat(x[next[i]], has_twin[i] ? x[twin[i]] : 0) + b)
// N = 1,000,000 half-edges, C = 64 (K = 2C = 128).
//
// Per block: gather a 128-row x 128-col neighbor tile into smem (each 64-float
// half-row is a contiguous 256B gather loaded by 16 lanes as float4), keep W
// transposed in smem, register-tiled GEMM: 256 threads x (8 rows x 4 cols),
// inner loop in packed fma.rn.f32x2 (FFMA2: 2 MACs/issue, bit-identical to FFMA).
//
// has_twin dtype is ambiguous (bool may be transported as int32 or as bytes);
// a tiny detector kernel resolves it at runtime into a __device__ flag.

#define C_OUT      64
#define K_DIM      128
#define M_TILE     128
#define THREADS    256
#define AS_STRIDE  132   // 128 + 4 pad; multiple of 4 floats for float4 ops

#define AS_FLOATS  (M_TILE * AS_STRIDE)
#define WT_FLOATS  (K_DIM * C_OUT)
#define SMEM_BYTES ((AS_FLOATS + WT_FLOATS) * (int)sizeof(float))

__device__ int g_ht_byte_mode;   // 1 -> has_twin is byte-bool, 0 -> int32

__global__ void detect_bool_mode_kernel(const unsigned int* __restrict__ ht_words)
{
    // 32 threads scan 1024 words. int32-bool: every word is 0 or 1.
    // byte-bool: P(word <= 1) ~ 1/8 per word -> certain detection over 1024.
    unsigned int any_big = 0;
    for (int i = threadIdx.x; i < 1024; i += 32)
        any_big |= (ht_words[i] > 1u);
    any_big = __ballot_sync(0xFFFFFFFFu, any_big != 0);
    if (threadIdx.x == 0)
        g_ht_byte_mode = (any_big != 0) ? 1 : 0;
}

__device__ __forceinline__ unsigned long long pack_dup(float a) {
    unsigned long long r;
    asm("mov.b64 %0, {%1, %1};" : "=l"(r) : "f"(a));
    return r;
}
__device__ __forceinline__ unsigned long long ffma2(unsigned long long a,
                                                    unsigned long long b,
                                                    unsigned long long c) {
    unsigned long long d;
    asm("fma.rn.f32x2 %0, %1, %2, %3;" : "=l"(d) : "l"(a), "l"(b), "l"(c));
    return d;
}
__device__ __forceinline__ float2 unpack2(unsigned long long v) {
    float2 f;
    asm("mov.b64 {%0, %1}, %2;" : "=f"(f.x), "=f"(f.y) : "l"(v));
    return f;
}

__global__ void __launch_bounds__(THREADS, 2)
halfedge_conv_kernel(const float* __restrict__ x,
                     const int* __restrict__ next_idx,
                     const int* __restrict__ twin_idx,
                     const int* __restrict__ has_twin,   // int32 or byte-bool (see flag)
                     const float* __restrict__ W,        // [64][128] row-major
                     const float* __restrict__ b,        // [64]
                     float* __restrict__ out,            // [N][64]
                     int n)
{
    extern __shared__ float smem[];
    float* As = smem;                 // [M_TILE][AS_STRIDE]
    float* Wt = smem + AS_FLOATS;     // Wt[k*64+c] = W[c*128+k]

    const int tid = threadIdx.x;
    const int rowBase = blockIdx.x * M_TILE;
    const int byte_mode = g_ht_byte_mode;
    const unsigned char* ht_bytes = (const unsigned char*)has_twin;

    // ---- Load W transposed into smem (coalesced read of W) ----
    #pragma unroll
    for (int i = tid; i < WT_FLOATS; i += THREADS) {
        int c = i >> 7;          // 0..63
        int k = i & 127;         // 0..127
        Wt[k * C_OUT + c] = W[i];
    }

    // ---- Gather neighbor tile: 256 (row, half) pairs, each 64 floats ----
    {
        const int grp = tid >> 4;     // 0..15
        const int l   = tid & 15;     // float4 lane within the 64-float half
        #pragma unroll
        for (int p = grp; p < 2 * M_TILE; p += 16) {
            int row  = p >> 1;
            int half = p & 1;
            int gRow = rowBase + row;
            float4 v = make_float4(0.f, 0.f, 0.f, 0.f);
            if (gRow < n) {
                int idx;
                bool valid;
                if (half == 0) { idx = next_idx[gRow]; valid = true; }
                else {
                    valid = byte_mode ? (ht_bytes[gRow] != 0)
                                      : (has_twin[gRow] != 0);
                    idx = valid ? twin_idx[gRow] : 0;
                }
                if (valid) {
                    const float4* src =
                        reinterpret_cast<const float4*>(x + (size_t)idx * C_OUT);
                    v = src[l];
                }
            }
            float4* dst = reinterpret_cast<float4*>(&As[row * AS_STRIDE + half * C_OUT]);
            dst[l] = v;
        }
    }

    __syncthreads();

    // ---- Register-tiled GEMM: thread (ty, tx) -> rows ty*8..+7, cols tx*4..+3
    const int tx = tid & 15;   // channel group (4 channels = 2 f32x2 pairs)
    const int ty = tid >> 4;   // row group (8 rows)
    const int arow = ty * 8;

    // acc2[r][0] packs cols (4tx, 4tx+1); acc2[r][1] packs (4tx+2, 4tx+3)
    unsigned long long acc2[8][2];
    #pragma unroll
    for (int r = 0; r < 8; r++) { acc2[r][0] = 0ull; acc2[r][1] = 0ull; }

    const float* a0 = &As[arow * AS_STRIDE];
    const float* w0 = &Wt[tx * 4];

    #pragma unroll 2
    for (int k4 = 0; k4 < K_DIM; k4 += 4) {
        // one LDS.128 per row per 4 k-steps
        float4 av[8];
        #pragma unroll
        for (int r = 0; r < 8; r++)
            av[r] = *reinterpret_cast<const float4*>(&a0[r * AS_STRIDE + k4]);

        #pragma unroll
        for (int kk = 0; kk < 4; kk++) {
            // Wt row (k4+kk): 16 lanes read 16 consecutive 16B chunks, conflict-free
            ulonglong2 w = *reinterpret_cast<const ulonglong2*>(
                               &w0[(k4 + kk) * C_OUT]);
            #pragma unroll
            for (int r = 0; r < 8; r++) {
                float a = (kk == 0) ? av[r].x : (kk == 1) ? av[r].y
                        : (kk == 2) ? av[r].z : av[r].w;
                unsigned long long aa = pack_dup(a);
                acc2[r][0] = ffma2(aa, w.x, acc2[r][0]);
                acc2[r][1] = ffma2(aa, w.y, acc2[r][1]);
            }
        }
    }

    // ---- Epilogue: bias + relu, float4 coalesced store ----
    float4 bv = reinterpret_cast<const float4*>(b)[tx];
    #pragma unroll
    for (int r = 0; r < 8; r++) {
        int gRow = rowBase + arow + r;
        if (gRow < n) {
            float2 p0 = unpack2(acc2[r][0]);
            float2 p1 = unpack2(acc2[r][1]);
            float4 o;
            o.x = fmaxf(p0.x + bv.x, 0.f);
            o.y = fmaxf(p0.y + bv.y, 0.f);
            o.z = fmaxf(p1.x + bv.z, 0.f);
            o.w = fmaxf(p1.y + bv.w, 0.f);
            reinterpret_cast<float4*>(out + (size_t)gRow * C_OUT)[tx] = o;
        }
    }
}

extern "C" void kernel_launch(void* const* d_in, const int* in_sizes, int n_in,
                              void* d_out, int out_size)
{
    const float* x        = (const float*)d_in[0];
    const int*   next_idx = (const int*)d_in[1];
    const int*   twin_idx = (const int*)d_in[2];
    const int*   has_twin = (const int*)d_in[3];
    const float* W        = (const float*)d_in[4];
    const float* b        = (const float*)d_in[5];
    float*       out      = (float*)d_out;

    int n = in_sizes[1];   // N half-edges (next_idx element count)

    detect_bool_mode_kernel<<<1, 32>>>((const unsigned int*)has_twin);

    cudaFuncSetAttribute(halfedge_conv_kernel,
                         cudaFuncAttributeMaxDynamicSharedMemorySize, SMEM_BYTES);

    int grid = (n + M_TILE - 1) / M_TILE;
    halfedge_conv_kernel<<<grid, THREADS, SMEM_BYTES>>>(
        x, next_idx, twin_idx, has_twin, W, b, out, n);
}

// round 12
// speedup vs baseline: 1.2249x; 1.2249x over previous
#include <cuda_runtime.h>
#include <cuda_bf16.h>
#include <cstdint>

// HalfEdgeConv: out[i] = relu(W @ concat(x[next[i]], has_twin[i] ? x[twin[i]] : 0) + b)
// N = 1M, C = 64, K = 2C = 128.
//
// Primary path: split-bf16 tensor MMA via mma.sync.m16n8k16 (sm_80+ ISA —
// compiles under compute_103; tcgen05 does NOT). acc = Ah*Wh + Ah*Wl + Al*Wh,
// fp32 accum, rel_err ~1e-5. Deterministic on-device verify of 128 sampled
// rows; on mismatch a proven FFMA2 fallback recomputes everything.

#define M_TILE   128
#define THREADS  256

// bf16 tile strides: 136 bf16 per row (128 + 8 pad) = 272 B -> conflict-free ldmatrix
#define AROW_B   272
// smem byte offsets (mma kernel)
#define SM_BIAS  0
#define SM_A_HI  1024
#define SM_A_LO  (SM_A_HI + M_TILE * AROW_B)     // +34816
#define SM_W_HI  (SM_A_LO + M_TILE * AROW_B)
#define SM_W_LO  (SM_W_HI + 64 * AROW_B)         // +17408
#define SM_TOTAL (SM_W_LO + 64 * AROW_B)         // 105472 B -> 2 CTAs/SM

// fallback kernel smem
#define AS_STRIDE  132
#define AS_FLOATS  (M_TILE * AS_STRIDE)
#define WT_FLOATS  (128 * 64)
#define FB_SMEM_BYTES ((AS_FLOATS + WT_FLOATS) * (int)sizeof(float))

__device__ int g_ht_byte_mode;
__device__ int g_fallback;

__global__ void detect_bool_mode_kernel(const unsigned int* __restrict__ ht_words)
{
    unsigned int any_big = 0;
    for (int i = threadIdx.x; i < 1024; i += 32)
        any_big |= (ht_words[i] > 1u);
    any_big = __ballot_sync(0xFFFFFFFFu, any_big != 0);
    if (threadIdx.x == 0) {
        g_ht_byte_mode = (any_big != 0) ? 1 : 0;
        g_fallback = 0;
    }
}

// ---------------- helpers ----------------
__device__ __forceinline__ uint32_t smem_u32(const void* p) {
    uint32_t a;
    asm("{ .reg .u64 t; cvta.to.shared.u64 t, %1; cvt.u32.u64 %0, t; }"
        : "=r"(a) : "l"(p));
    return a;
}
__device__ __forceinline__ void ldsm_x4(uint32_t& r0, uint32_t& r1,
                                        uint32_t& r2, uint32_t& r3, uint32_t addr) {
    asm volatile("ldmatrix.sync.aligned.m8n8.x4.shared.b16 {%0,%1,%2,%3}, [%4];"
                 : "=r"(r0), "=r"(r1), "=r"(r2), "=r"(r3) : "r"(addr));
}
__device__ __forceinline__ void ldsm_x2(uint32_t& r0, uint32_t& r1, uint32_t addr) {
    asm volatile("ldmatrix.sync.aligned.m8n8.x2.shared.b16 {%0,%1}, [%2];"
                 : "=r"(r0), "=r"(r1) : "r"(addr));
}
__device__ __forceinline__ void mma_16816(float* c, uint32_t a0, uint32_t a1,
                                          uint32_t a2, uint32_t a3,
                                          uint32_t b0, uint32_t b1) {
    asm volatile("mma.sync.aligned.m16n8k16.row.col.f32.bf16.bf16.f32 "
                 "{%0,%1,%2,%3}, {%4,%5,%6,%7}, {%8,%9}, {%0,%1,%2,%3};"
                 : "+f"(c[0]), "+f"(c[1]), "+f"(c[2]), "+f"(c[3])
                 : "r"(a0), "r"(a1), "r"(a2), "r"(a3), "r"(b0), "r"(b1));
}
__device__ __forceinline__ void cvt_split(float4 v, uint2& hi, uint2& lo) {
    __nv_bfloat162 h01 = __floats2bfloat162_rn(v.x, v.y);
    __nv_bfloat162 h23 = __floats2bfloat162_rn(v.z, v.w);
    float rx = v.x - __low2float(h01),  ry = v.y - __high2float(h01);
    float rz = v.z - __low2float(h23),  rw = v.w - __high2float(h23);
    __nv_bfloat162 l01 = __floats2bfloat162_rn(rx, ry);
    __nv_bfloat162 l23 = __floats2bfloat162_rn(rz, rw);
    hi.x = *reinterpret_cast<uint32_t*>(&h01);
    hi.y = *reinterpret_cast<uint32_t*>(&h23);
    lo.x = *reinterpret_cast<uint32_t*>(&l01);
    lo.y = *reinterpret_cast<uint32_t*>(&l23);
}

// ================= primary: mma.sync split-bf16 =================
__global__ void __launch_bounds__(THREADS, 2)
halfedge_mma_kernel(const float* __restrict__ x,
                    const int* __restrict__ next_idx,
                    const int* __restrict__ twin_idx,
                    const int* __restrict__ has_twin,
                    const float* __restrict__ W,     // [64][128]
                    const float* __restrict__ b,
                    float* __restrict__ out,
                    int n)
{
    extern __shared__ char smem[];
    const uint32_t sbase = smem_u32(smem);
    const int tid = threadIdx.x;
    const int wid = tid >> 5;
    const int lid = tid & 31;
    const int rowBase = blockIdx.x * M_TILE;
    const int byte_mode = g_ht_byte_mode;
    const unsigned char* ht_bytes = (const unsigned char*)has_twin;

    if (tid < 64) *reinterpret_cast<float*>(smem + SM_BIAS + tid * 4) = b[tid];

    // ---- W -> bf16 hi/lo [64 rows x 128 k], padded rows ----
    #pragma unroll
    for (int f = tid; f < 2048; f += THREADS) {      // 2048 float4 = 64x128 fp32
        int nr = f >> 5, l = f & 31;                 // W row, float4 lane (k = l*4)
        float4 wv = reinterpret_cast<const float4*>(W)[f];
        uint2 hi, lo; cvt_split(wv, hi, lo);
        uint32_t off = (uint32_t)nr * AROW_B + (uint32_t)l * 8u;
        *reinterpret_cast<uint2*>(smem + SM_W_HI + off) = hi;
        *reinterpret_cast<uint2*>(smem + SM_W_LO + off) = lo;
    }

    // ---- Gather + convert A tile [128 rows x 128 k] ----
    {
        const int grp = tid >> 4;
        const int l   = tid & 15;
        int idxs[16]; unsigned vmask = 0;
        #pragma unroll
        for (int i = 0; i < 16; i++) {               // front-batch index loads
            int p = grp + 16 * i, row = p >> 1, half = p & 1;
            int gRow = rowBase + row;
            int idx = 0, vld = 0;
            if (gRow < n) {
                if (half == 0) { idx = next_idx[gRow]; vld = 1; }
                else {
                    vld = byte_mode ? (ht_bytes[gRow] != 0) : (has_twin[gRow] != 0);
                    idx = vld ? twin_idx[gRow] : 0;
                }
            }
            idxs[i] = idx;
            vmask |= (unsigned)vld << i;
        }
        #pragma unroll
        for (int i = 0; i < 16; i++) {
            int p = grp + 16 * i, row = p >> 1, half = p & 1;
            float4 v = make_float4(0.f, 0.f, 0.f, 0.f);
            if ((vmask >> i) & 1)
                v = reinterpret_cast<const float4*>(x + (size_t)idxs[i] * 64)[l];
            uint2 hi, lo; cvt_split(v, hi, lo);
            uint32_t off = (uint32_t)row * AROW_B + (uint32_t)half * 128u
                         + (uint32_t)l * 8u;
            *reinterpret_cast<uint2*>(smem + SM_A_HI + off) = hi;
            *reinterpret_cast<uint2*>(smem + SM_A_LO + off) = lo;
        }
    }

    __syncthreads();

    // ---- MMA: warp w computes rows [w*16, w*16+16) x 64 cols ----
    float acc[8][4];
    #pragma unroll
    for (int nb = 0; nb < 8; nb++)
        #pragma unroll
        for (int i = 0; i < 4; i++) acc[nb][i] = 0.f;

    {
        uint32_t arow = (uint32_t)(wid * 16 + (lid & 15));
        uint32_t akoff = (uint32_t)(lid >> 4) * 16u;            // bytes: (l>>4)*8 bf16
        uint32_t aAhi = sbase + SM_A_HI + arow * AROW_B + akoff;
        uint32_t aAlo = sbase + SM_A_LO + arow * AROW_B + akoff;
        uint32_t wrow = (uint32_t)(lid & 7);
        uint32_t wkoff = (uint32_t)((lid >> 3) & 1) * 16u;
        uint32_t aWhi = sbase + SM_W_HI + wrow * AROW_B + wkoff;
        uint32_t aWlo = sbase + SM_W_LO + wrow * AROW_B + wkoff;

        #pragma unroll
        for (int kk = 0; kk < 8; kk++) {
            uint32_t ko = (uint32_t)kk * 32u;                   // 16 bf16 = 32 B
            uint32_t ah0, ah1, ah2, ah3, al0, al1, al2, al3;
            ldsm_x4(ah0, ah1, ah2, ah3, aAhi + ko);
            ldsm_x4(al0, al1, al2, al3, aAlo + ko);
            #pragma unroll
            for (int nb = 0; nb < 8; nb++) {
                uint32_t wo = (uint32_t)nb * (8u * AROW_B) + ko;
                uint32_t bh0, bh1, bl0, bl1;
                ldsm_x2(bh0, bh1, aWhi + wo);
                ldsm_x2(bl0, bl1, aWlo + wo);
                mma_16816(acc[nb], ah0, ah1, ah2, ah3, bh0, bh1);  // Ah*Wh
                mma_16816(acc[nb], ah0, ah1, ah2, ah3, bl0, bl1);  // Ah*Wl
                mma_16816(acc[nb], al0, al1, al2, al3, bh0, bh1);  // Al*Wh
            }
        }
    }

    // ---- Epilogue: bias+relu, stage through own A_hi rows (warp-local, dead),
    //      then coalesced float4 stores ----
    {
        float* stg = reinterpret_cast<float*>(smem + SM_A_HI
                                              + (uint32_t)wid * 16u * AROW_B);
        const float* sb = reinterpret_cast<const float*>(smem + SM_BIAS);
        const int gr = lid >> 2;          // 0..7  (row group)
        const int gc = (lid & 3) * 2;     // col pair base within n-tile
        #pragma unroll
        for (int nb = 0; nb < 8; nb++) {
            int c = nb * 8 + gc;
            float b0 = sb[c], b1 = sb[c + 1];
            float2 lo2, hi2;
            lo2.x = fmaxf(acc[nb][0] + b0, 0.f);
            lo2.y = fmaxf(acc[nb][1] + b1, 0.f);
            hi2.x = fmaxf(acc[nb][2] + b0, 0.f);
            hi2.y = fmaxf(acc[nb][3] + b1, 0.f);
            *reinterpret_cast<float2*>(&stg[gr * 68 + c])       = lo2;
            *reinterpret_cast<float2*>(&stg[(gr + 8) * 68 + c]) = hi2;
        }
        __syncwarp();

        const int sub = lid >> 4, ll = lid & 15;   // 2 rows/pass, 16 lanes each
        #pragma unroll
        for (int pr = 0; pr < 8; pr++) {
            int rl = pr * 2 + sub;
            int gRow = rowBase + wid * 16 + rl;
            if (gRow < n) {
                float4 v = *reinterpret_cast<float4*>(&stg[rl * 68 + ll * 4]);
                reinterpret_cast<float4*>(out + (size_t)gRow * 64)[ll] = v;
            }
        }
    }
}

// ================= verify: 128 sampled rows, scalar fp32 =================
__global__ void verify_kernel(const float* __restrict__ x,
                              const int* __restrict__ next_idx,
                              const int* __restrict__ twin_idx,
                              const int* __restrict__ has_twin,
                              const float* __restrict__ W,
                              const float* __restrict__ b,
                              const float* __restrict__ out,
                              int n)
{
    const int byte_mode = g_ht_byte_mode;
    const unsigned char* ht_bytes = (const unsigned char*)has_twin;
    int row = (int)(((unsigned)threadIdx.x * 2654435761u) % (unsigned)n);

    int ni = next_idx[row];
    int vld = byte_mode ? (ht_bytes[row] != 0) : (has_twin[row] != 0);
    int ti = vld ? twin_idx[row] : 0;

    int bad = 0;
    for (int c = 0; c < 64; c++) {
        float acc = b[c];
        const float* wr = W + c * 128;
        for (int k = 0; k < 64; k++)
            acc = fmaf(x[(size_t)ni * 64 + k], wr[k], acc);
        if (vld)
            for (int k = 0; k < 64; k++)
                acc = fmaf(x[(size_t)ti * 64 + k], wr[64 + k], acc);
        float ref = fmaxf(acc, 0.f);
        float got = out[(size_t)row * 64 + c];
        float tol = 1e-3f * fmaxf(fabsf(ref), 0.1f);
        if (fabsf(got - ref) > tol) bad = 1;
    }
    if (__syncthreads_or(bad) && threadIdx.x == 0)
        g_fallback = 1;
}

// ================= fallback: proven FFMA2 kernel, flag-gated =================
__device__ __forceinline__ unsigned long long pack_dup(float a) {
    unsigned long long r;
    asm("mov.b64 %0, {%1, %1};" : "=l"(r) : "f"(a));
    return r;
}
__device__ __forceinline__ unsigned long long ffma2(unsigned long long a,
                                                    unsigned long long b,
                                                    unsigned long long c) {
    unsigned long long d;
    asm("fma.rn.f32x2 %0, %1, %2, %3;" : "=l"(d) : "l"(a), "l"(b), "l"(c));
    return d;
}
__device__ __forceinline__ float2 unpack2(unsigned long long v) {
    float2 f;
    asm("mov.b64 {%0, %1}, %2;" : "=f"(f.x), "=f"(f.y) : "l"(v));
    return f;
}

__global__ void __launch_bounds__(THREADS, 2)
halfedge_fallback_kernel(const float* __restrict__ x,
                         const int* __restrict__ next_idx,
                         const int* __restrict__ twin_idx,
                         const int* __restrict__ has_twin,
                         const float* __restrict__ W,
                         const float* __restrict__ b,
                         float* __restrict__ out,
                         int n)
{
    if (g_fallback == 0) return;

    extern __shared__ float fsmem[];
    float* As = fsmem;
    float* Wt = fsmem + AS_FLOATS;

    const int tid = threadIdx.x;
    const int rowBase = blockIdx.x * M_TILE;
    const int byte_mode = g_ht_byte_mode;
    const unsigned char* ht_bytes = (const unsigned char*)has_twin;

    #pragma unroll
    for (int i = tid; i < WT_FLOATS; i += THREADS) {
        int c = i >> 7, k = i & 127;
        Wt[k * 64 + c] = W[i];
    }
    {
        const int grp = tid >> 4;
        const int l   = tid & 15;
        #pragma unroll
        for (int p = grp; p < 2 * M_TILE; p += 16) {
            int row = p >> 1, half = p & 1;
            int gRow = rowBase + row;
            float4 v = make_float4(0.f, 0.f, 0.f, 0.f);
            if (gRow < n) {
                int idx; bool valid;
                if (half == 0) { idx = next_idx[gRow]; valid = true; }
                else {
                    valid = byte_mode ? (ht_bytes[gRow] != 0) : (has_twin[gRow] != 0);
                    idx = valid ? twin_idx[gRow] : 0;
                }
                if (valid)
                    v = reinterpret_cast<const float4*>(x + (size_t)idx * 64)[l];
            }
            reinterpret_cast<float4*>(&As[row * AS_STRIDE + half * 64])[l] = v;
        }
    }
    __syncthreads();

    const int tx = tid & 15, ty = tid >> 4, arow = ty * 8;
    unsigned long long acc2[8][2];
    #pragma unroll
    for (int r = 0; r < 8; r++) { acc2[r][0] = 0ull; acc2[r][1] = 0ull; }

    const float* a0 = &As[arow * AS_STRIDE];
    const float* w0 = &Wt[tx * 4];

    #pragma unroll 2
    for (int k4 = 0; k4 < 128; k4 += 4) {
        float4 av[8];
        #pragma unroll
        for (int r = 0; r < 8; r++)
            av[r] = *reinterpret_cast<const float4*>(&a0[r * AS_STRIDE + k4]);
        #pragma unroll
        for (int kk = 0; kk < 4; kk++) {
            ulonglong2 w = *reinterpret_cast<const ulonglong2*>(&w0[(k4 + kk) * 64]);
            #pragma unroll
            for (int r = 0; r < 8; r++) {
                float a = (kk == 0) ? av[r].x : (kk == 1) ? av[r].y
                        : (kk == 2) ? av[r].z : av[r].w;
                unsigned long long aa = pack_dup(a);
                acc2[r][0] = ffma2(aa, w.x, acc2[r][0]);
                acc2[r][1] = ffma2(aa, w.y, acc2[r][1]);
            }
        }
    }

    float4 bv = reinterpret_cast<const float4*>(b)[tx];
    #pragma unroll
    for (int r = 0; r < 8; r++) {
        int gRow = rowBase + arow + r;
        if (gRow < n) {
            float2 p0 = unpack2(acc2[r][0]);
            float2 p1 = unpack2(acc2[r][1]);
            float4 o;
            o.x = fmaxf(p0.x + bv.x, 0.f);
            o.y = fmaxf(p0.y + bv.y, 0.f);
            o.z = fmaxf(p1.x + bv.z, 0.f);
            o.w = fmaxf(p1.y + bv.w, 0.f);
            reinterpret_cast<float4*>(out + (size_t)gRow * 64)[tx] = o;
        }
    }
}

extern "C" void kernel_launch(void* const* d_in, const int* in_sizes, int n_in,
                              void* d_out, int out_size)
{
    const float* x        = (const float*)d_in[0];
    const int*   next_idx = (const int*)d_in[1];
    const int*   twin_idx = (const int*)d_in[2];
    const int*   has_twin = (const int*)d_in[3];
    const float* W        = (const float*)d_in[4];
    const float* b        = (const float*)d_in[5];
    float*       out      = (float*)d_out;

    int n = in_sizes[1];
    int grid = (n + M_TILE - 1) / M_TILE;

    detect_bool_mode_kernel<<<1, 32>>>((const unsigned int*)has_twin);

    cudaFuncSetAttribute(halfedge_mma_kernel,
                         cudaFuncAttributeMaxDynamicSharedMemorySize, SM_TOTAL);
    halfedge_mma_kernel<<<grid, THREADS, SM_TOTAL>>>(
        x, next_idx, twin_idx, has_twin, W, b, out, n);

    verify_kernel<<<1, 128>>>(x, next_idx, twin_idx, has_twin, W, b, out, n);

    cudaFuncSetAttribute(halfedge_fallback_kernel,
                         cudaFuncAttributeMaxDynamicSharedMemorySize, FB_SMEM_BYTES);
    halfedge_fallback_kernel<<<grid, THREADS, FB_SMEM_BYTES>>>(
        x, next_idx, twin_idx, has_twin, W, b, out, n);
}